// round 2
// baseline (speedup 1.0000x reference)
#include <cuda_runtime.h>
#include <stdint.h>

#define N_LABELS 1000
#define THREADS 256
#define UNROLL 4

// Modes:
//  0: mask written as float32 at out + n        (out_size == 2*n)   <- actual layout per R1
//  1: mask written as int16  at (short*)(out+n) (out_size == n + n/2)
//  2: no mask output (out_size == n)
template <int MODE>
__global__ void __launch_bounds__(THREADS)
vessel_fuse_kernel(const int4* __restrict__ labels4,
                   const float4* __restrict__ par4,
                   const int* __restrict__ keep_mask,
                   const float* __restrict__ intensity_lut,
                   float4* __restrict__ out4,
                   float4* __restrict__ maskf4,
                   uint2* __restrict__ mask16x4,
                   int nv,           // number of vec4 groups
                   int n)            // total voxels
{
    __shared__ float s_mult[N_LABELS];

    // Combined LUT: kept vessel -> intensity (never exactly 1.0f by construction:
    // intensities are in [0,0.7) U [1.3,2)); background / pruned -> 1.0f.
    // Mask is then derived as (mult != 1.0f), eliminating a second LDS gather.
    for (int i = threadIdx.x; i < N_LABELS; i += THREADS) {
        bool k = (i > 0) && (keep_mask[i] > 0);
        s_mult[i] = k ? __ldg(&intensity_lut[i]) : 1.0f;
    }
    __syncthreads();

    const int stride = gridDim.x * THREADS;
    const int idx = blockIdx.x * THREADS + threadIdx.x;

    int i = idx;
    // Main unrolled loop: batch all loads first (deep L1tex queue / high MLP),
    // then compute + store. All accesses per LDG are fully coalesced.
    for (; i + (UNROLL - 1) * stride < nv; i += UNROLL * stride) {
        int4   L[UNROLL];
        float4 P[UNROLL];
#pragma unroll
        for (int k = 0; k < UNROLL; k++) {
            L[k] = __ldcs(&labels4[i + k * stride]);
            P[k] = __ldcs(&par4[i + k * stride]);
        }
#pragma unroll
        for (int k = 0; k < UNROLL; k++) {
            float m0 = s_mult[L[k].x];
            float m1 = s_mult[L[k].y];
            float m2 = s_mult[L[k].z];
            float m3 = s_mult[L[k].w];

            float4 O;
            O.x = P[k].x * m0;
            O.y = P[k].y * m1;
            O.z = P[k].z * m2;
            O.w = P[k].w * m3;
            __stcs(&out4[i + k * stride], O);

            if (MODE == 0) {
                float4 M;
                M.x = (m0 != 1.0f) ? 1.0f : 0.0f;
                M.y = (m1 != 1.0f) ? 1.0f : 0.0f;
                M.z = (m2 != 1.0f) ? 1.0f : 0.0f;
                M.w = (m3 != 1.0f) ? 1.0f : 0.0f;
                __stcs(&maskf4[i + k * stride], M);
            } else if (MODE == 1) {
                uint2 mm;
                mm.x = (uint32_t)(m0 != 1.0f) | ((uint32_t)(m1 != 1.0f) << 16);
                mm.y = (uint32_t)(m2 != 1.0f) | ((uint32_t)(m3 != 1.0f) << 16);
                __stcs(&mask16x4[i + k * stride], mm);
            }
        }
    }
    // Remainder vec4 groups
    for (; i < nv; i += stride) {
        int4   L = __ldcs(&labels4[i]);
        float4 P = __ldcs(&par4[i]);
        float m0 = s_mult[L.x], m1 = s_mult[L.y], m2 = s_mult[L.z], m3 = s_mult[L.w];
        float4 O = {P.x * m0, P.y * m1, P.z * m2, P.w * m3};
        __stcs(&out4[i], O);
        if (MODE == 0) {
            float4 M = {(m0 != 1.0f) ? 1.0f : 0.0f, (m1 != 1.0f) ? 1.0f : 0.0f,
                        (m2 != 1.0f) ? 1.0f : 0.0f, (m3 != 1.0f) ? 1.0f : 0.0f};
            __stcs(&maskf4[i], M);
        } else if (MODE == 1) {
            uint2 mm;
            mm.x = (uint32_t)(m0 != 1.0f) | ((uint32_t)(m1 != 1.0f) << 16);
            mm.y = (uint32_t)(m2 != 1.0f) | ((uint32_t)(m3 != 1.0f) << 16);
            __stcs(&mask16x4[i], mm);
        }
    }

    // Scalar tail (n not divisible by 4) — first few global threads.
    int tail = n - nv * 4;
    if (idx < tail) {
        int j = nv * 4 + idx;
        int lab = ((const int*)labels4)[j];
        float p = ((const float*)par4)[j];
        float m = s_mult[lab];
        ((float*)out4)[j] = p * m;
        if (MODE == 0) ((float*)maskf4)[j] = (m != 1.0f) ? 1.0f : 0.0f;
        else if (MODE == 1) ((short*)mask16x4)[j] = (short)(m != 1.0f);
    }
}

extern "C" void kernel_launch(void* const* d_in, const int* in_sizes, int n_in,
                              void* d_out, int out_size)
{
    const int*   labels = (const int*)d_in[0];
    const int*   keep   = (const int*)d_in[1];
    const float* lut    = (const float*)d_in[2];
    const float* par    = (const float*)d_in[3];
    float*       out    = (float*)d_out;

    const int n  = in_sizes[0];       // D^3 voxels
    const int nv = n / 4;

    // Single resident wave: 152 SMs x 4 blocks of 8 warps = full occupancy,
    // LUT loaded once per resident block only.
    int blocks = 152 * 4;
    int needed = (nv + THREADS - 1) / THREADS;
    if (blocks > needed) blocks = needed;
    if (blocks < 1) blocks = 1;

    const int4*   labels4 = (const int4*)labels;
    const float4* par4    = (const float4*)par;
    float4*       out4    = (float4*)out;

    if (out_size >= 2 * n) {
        float4* maskf4 = (float4*)(out + n);
        vessel_fuse_kernel<0><<<blocks, THREADS>>>(labels4, par4, keep, lut,
                                                   out4, maskf4, nullptr, nv, n);
    } else if (out_size >= n + n / 2) {
        uint2* mask16x4 = (uint2*)(out + n);
        vessel_fuse_kernel<1><<<blocks, THREADS>>>(labels4, par4, keep, lut,
                                                   out4, nullptr, mask16x4, nv, n);
    } else {
        vessel_fuse_kernel<2><<<blocks, THREADS>>>(labels4, par4, keep, lut,
                                                   out4, nullptr, nullptr, nv, n);
    }
}